// round 13
// baseline (speedup 1.0000x reference)
#include <cuda_runtime.h>
#include <cuda_bf16.h>
#include <cstdint>

// Problem constants
#define CB      4          // batches
#define N1C     16384      // queries per batch
#define N2C     4096       // points per batch
#define NQ      (CB*N1C)   // 65536
#define NP      (CB*N2C)   // 16384
#define COUTC   256
#define GRIDG   16
#define NCELL   (GRIDG*GRIDG*GRIDG)  // 4096

__device__ __forceinline__ uint32_t smem_to_u32(const void* smem_ptr) {
    uint32_t addr;
    asm("{ .reg .u64 tmp; cvta.to.shared.u64 tmp, %1; cvt.u32.u64 %0, tmp; }"
        : "=r"(addr) : "l"(smem_ptr));
    return addr;
}
__device__ __forceinline__ void ldm_x4(uint32_t* r, uint32_t addr) {
    asm volatile("ldmatrix.sync.aligned.m8n8.x4.shared.b16 {%0,%1,%2,%3}, [%4];"
        : "=r"(r[0]), "=r"(r[1]), "=r"(r[2]), "=r"(r[3]) : "r"(addr));
}
__device__ __forceinline__ void ldm_x2(uint32_t* r, uint32_t addr) {
    asm volatile("ldmatrix.sync.aligned.m8n8.x2.shared.b16 {%0,%1}, [%2];"
        : "=r"(r[0]), "=r"(r[1]) : "r"(addr));
}
__device__ __forceinline__ void mma_bf16(float* c, const uint32_t* a, const uint32_t* b) {
    asm volatile("mma.sync.aligned.m16n8k16.row.col.f32.bf16.bf16.f32 "
        "{%0,%1,%2,%3}, {%4,%5,%6,%7}, {%8,%9}, {%0,%1,%2,%3};"
        : "+f"(c[0]), "+f"(c[1]), "+f"(c[2]), "+f"(c[3])
        : "r"(a[0]), "r"(a[1]), "r"(a[2]), "r"(a[3]), "r"(b[0]), "r"(b[1]));
}
__device__ __forceinline__ void cp_async16(uint32_t dst, const void* src) {
    asm volatile("cp.async.cg.shared.global [%0], [%1], 16;" :: "r"(dst), "l"(src));
}
#define CP_COMMIT() asm volatile("cp.async.commit_group;" ::: "memory")
#define CP_WAIT0()  asm volatile("cp.async.wait_group 0;" ::: "memory")

__device__ __forceinline__ uint32_t pack_bf2(__nv_bfloat16 a, __nv_bfloat16 b) {
    __nv_bfloat162 t(a, b);
    return *reinterpret_cast<uint32_t*>(&t);
}

// ---------------- device scratch (static — no allocation allowed) ------------
__device__ float  g_f2pre[NP * COUTC];         // 16 MB pre-activation of branch 2
__device__ __nv_bfloat16 g_W1h[256 * 256];     // transposed [N][K]
__device__ __nv_bfloat16 g_W1l[256 * 256];
__device__ __nv_bfloat16 g_W2h[256 * 512];
__device__ __nv_bfloat16 g_W2l[256 * 512];
__device__ float  g_psum1[512 * COUTC];
__device__ float  g_psq1 [512 * COUTC];
__device__ float  g_psum2[128 * COUTC];
__device__ float  g_psq2 [128 * COUTC];
__device__ float  g_mean1[COUTC], g_rstd1[COUTC];
__device__ float  g_mean2[COUTC], g_rstd2[COUTC];
__device__ int    g_cnt[CB * NCELL];
__device__ int    g_cellStart[CB * (NCELL + 1)];
__device__ int    g_cellPtr[CB * NCELL];
__device__ float4 g_sortedPts[CB * N2C];       // x,y,z,|p|^2  (cell-sorted)
__device__ int    g_sortedIdx[CB * N2C];       // original row index (global)
__device__ int    g_qcnt[CB * NCELL];
__device__ int    g_qptr[CB * NCELL];
__device__ float4 g_sortedQ[NQ];               // x,y,z,|q|^2  (cell-sorted queries)
__device__ int    g_sortedQid[NQ];
__device__ int    g_knnIdx[NQ * 3];
__device__ float  g_knnW [NQ * 3];

// Both weight transposes + hi/lo splits in one launch.
__global__ __launch_bounds__(256) void wt_split_all_kernel(
    const float* __restrict__ W1, const float* __restrict__ W2)
{
    int i = blockIdx.x * 256 + threadIdx.x;
    if (i < 256 * 256) {
        int k = i >> 8, n = i & 255;
        float x = W1[i];
        __nv_bfloat16 h = __float2bfloat16_rn(x);
        g_W1h[n * 256 + k] = h;
        g_W1l[n * 256 + k] = __float2bfloat16_rn(x - __bfloat162float(h));
    } else {
        int j = i - 256 * 256;
        if (j >= 512 * 256) return;
        int k = j >> 8, n = j & 255;
        float x = W2[j];
        __nv_bfloat16 h = __float2bfloat16_rn(x);
        g_W2h[n * 512 + k] = h;
        g_W2l[n * 512 + k] = __float2bfloat16_rn(x - __bfloat162float(h));
    }
}

// ---------------- mma.sync bf16x3 GEMM: double-buffered pipeline -------------
#define PITCH 40                    // bf16 per smem row (80B — conflict-free ldmatrix)
#define TILEB 10240                 // one 128xPITCH bf16 tile in bytes
#define DB_AH 0
#define DB_AL TILEB
#define DB_BH (2*TILEB)
#define DB_BL (3*TILEB)
#define DB_BUF (4*TILEB)            // bytes per buffer (40960)
#define DB_S   (8*TILEB)            // sS after both buffers
#define DB_Q   (8*TILEB + 1024)
#define DB_TOTAL (8*TILEB + 2048)   // 83968 bytes

template<int K>
__device__ __forceinline__ void gemm_body(
    char* dsm, int bx, int by,
    const float* __restrict__ A,
    const __nv_bfloat16* __restrict__ Bh, const __nv_bfloat16* __restrict__ Bl,
    const float* __restrict__ bias, float* __restrict__ C,
    float* __restrict__ ps, float* __restrict__ pq)
{
    const uint32_t base = smem_to_u32(dsm);
    float (*sS)[32] = (float(*)[32])(dsm + DB_S);
    float (*sQ)[32] = (float(*)[32])(dsm + DB_Q);

    const int tid = threadIdx.x, lane = tid & 31, wid = tid >> 5;
    const int wm = wid & 1, wn = wid >> 1;      // warp grid: 2 (m) x 4 (n)
    const int m0 = by * 128, n0 = bx * 128;

    float acc[4][4][4];
#pragma unroll
    for (int i = 0; i < 4; i++)
#pragma unroll
        for (int j = 0; j < 4; j++)
#pragma unroll
            for (int k = 0; k < 4; k++) acc[i][j][k] = 0.f;

    const uint32_t aoff = ((uint32_t)((wm * 64 + (lane & 15)) * PITCH + (lane >> 4) * 8)) * 2;
    const uint32_t boff = ((uint32_t)((wn * 32 + (lane & 7)) * PITCH + ((lane >> 3) & 1) * 8)) * 2;

    float4 ra[4];   // A stage regs (held across compute in steady state)

    auto issueB = [&](int kt, int buf) {
        uint32_t dbh = base + buf * DB_BUF + DB_BH;
        uint32_t dbl = base + buf * DB_BUF + DB_BL;
        int k0 = kt * 32;
#pragma unroll
        for (int i = 0; i < 2; i++) {
            int fid = i * 256 + tid, r = fid >> 2, q = fid & 3;
            size_t gb = (size_t)(n0 + r) * K + k0 + q * 8;
            uint32_t so = (uint32_t)(r * PITCH + q * 8) * 2;
            cp_async16(dbh + so, Bh + gb);
            cp_async16(dbl + so, Bl + gb);
        }
        CP_COMMIT();
    };
    auto loadA = [&](int kt) {
        int k0 = kt * 32;
#pragma unroll
        for (int i = 0; i < 4; i++) {
            int fid = i * 256 + tid, r = fid >> 3, q = fid & 7;
            ra[i] = *(const float4*)(A + (size_t)(m0 + r) * K + k0 + q * 4);
        }
    };
    auto storeA = [&](int buf) {
        __nv_bfloat16* sAh = (__nv_bfloat16*)(dsm + buf * DB_BUF + DB_AH);
        __nv_bfloat16* sAl = (__nv_bfloat16*)(dsm + buf * DB_BUF + DB_AL);
#pragma unroll
        for (int i = 0; i < 4; i++) {
            int fid = i * 256 + tid, r = fid >> 3, q = fid & 7;
            float4 v = ra[i];
            __nv_bfloat16 h0 = __float2bfloat16_rn(v.x);
            __nv_bfloat16 h1 = __float2bfloat16_rn(v.y);
            __nv_bfloat16 h2 = __float2bfloat16_rn(v.z);
            __nv_bfloat16 h3 = __float2bfloat16_rn(v.w);
            __nv_bfloat16 l0 = __float2bfloat16_rn(v.x - __bfloat162float(h0));
            __nv_bfloat16 l1 = __float2bfloat16_rn(v.y - __bfloat162float(h1));
            __nv_bfloat16 l2 = __float2bfloat16_rn(v.z - __bfloat162float(h2));
            __nv_bfloat16 l3 = __float2bfloat16_rn(v.w - __bfloat162float(h3));
            int so = r * PITCH + q * 4;
            uint2 ph, pl;
            ph.x = pack_bf2(h0, h1); ph.y = pack_bf2(h2, h3);
            pl.x = pack_bf2(l0, l1); pl.y = pack_bf2(l2, l3);
            *(uint2*)(sAh + so) = ph;
            *(uint2*)(sAl + so) = pl;
        }
    };
    auto compute = [&](int buf) {
        uint32_t uAh = base + buf * DB_BUF + DB_AH;
        uint32_t uAl = base + buf * DB_BUF + DB_AL;
        uint32_t uBh = base + buf * DB_BUF + DB_BH;
        uint32_t uBl = base + buf * DB_BUF + DB_BL;
#pragma unroll
        for (int ks = 0; ks < 2; ks++) {
            uint32_t bfh[4][2], bfl[4][2];
#pragma unroll
            for (int nt = 0; nt < 4; nt++) {
                uint32_t o = boff + (uint32_t)(nt * 8 * PITCH + ks * 16) * 2;
                ldm_x2(bfh[nt], uBh + o);
                ldm_x2(bfl[nt], uBl + o);
            }
#pragma unroll
            for (int mt = 0; mt < 4; mt++) {
                uint32_t afh[4], afl[4];
                uint32_t o = aoff + (uint32_t)(mt * 16 * PITCH + ks * 16) * 2;
                ldm_x4(afh, uAh + o);
                ldm_x4(afl, uAl + o);
#pragma unroll
                for (int nt = 0; nt < 4; nt++) {
                    mma_bf16(acc[mt][nt], afh, bfh[nt]);
                    mma_bf16(acc[mt][nt], afh, bfl[nt]);
                    mma_bf16(acc[mt][nt], afl, bfh[nt]);
                }
            }
        }
    };

    const int NIT = K / 32;
    issueB(0, 0);
    loadA(0);
    storeA(0);
    CP_WAIT0();
    __syncthreads();

    for (int kt = 0; kt < NIT; kt++) {
        int cur = kt & 1, nxt = cur ^ 1;
        if (kt + 1 < NIT) {
            issueB(kt + 1, nxt);   // cp.async — overlaps compute below
            loadA(kt + 1);         // LDGs in flight across compute
        }
        compute(cur);
        if (kt + 1 < NIT) {
            storeA(nxt);           // convert + store into alternate buffer
            CP_WAIT0();
        }
        __syncthreads();
    }

    // epilogue: bias add, store C, per-block column sum/sumsq
    const int tr = lane >> 2, tc = (lane & 3) * 2;
    const int rbase = m0 + wm * 64, cbase = n0 + wn * 32;
#pragma unroll
    for (int nt = 0; nt < 4; nt++) {
        int col = cbase + nt * 8 + tc;
        float bx2 = bias[col], by2 = bias[col + 1];
        float s0 = 0.f, s1 = 0.f, q0 = 0.f, q1 = 0.f;
#pragma unroll
        for (int mt = 0; mt < 4; mt++) {
            int row = rbase + mt * 16 + tr;
            float v0 = acc[mt][nt][0] + bx2, v1 = acc[mt][nt][1] + by2;
            float v2 = acc[mt][nt][2] + bx2, v3 = acc[mt][nt][3] + by2;
            *(float2*)(C + (size_t)row * 256 + col) = make_float2(v0, v1);
            *(float2*)(C + (size_t)(row + 8) * 256 + col) = make_float2(v2, v3);
            s0 += v0 + v2; s1 += v1 + v3;
            q0 = fmaf(v0, v0, q0); q0 = fmaf(v2, v2, q0);
            q1 = fmaf(v1, v1, q1); q1 = fmaf(v3, v3, q1);
        }
#pragma unroll
        for (int off = 4; off <= 16; off <<= 1) {
            s0 += __shfl_xor_sync(0xffffffff, s0, off);
            s1 += __shfl_xor_sync(0xffffffff, s1, off);
            q0 += __shfl_xor_sync(0xffffffff, q0, off);
            q1 += __shfl_xor_sync(0xffffffff, q1, off);
        }
        if (tr == 0) {
            int lc = nt * 8 + tc;
            sS[wid][lc] = s0; sS[wid][lc + 1] = s1;
            sQ[wid][lc] = q0; sQ[wid][lc + 1] = q1;
        }
    }
    __syncthreads();
    if (tid < 128) {
        int wn2 = tid >> 5, col = tid & 31;
        float s = sS[wn2 * 2][col] + sS[wn2 * 2 + 1][col];
        float q = sQ[wn2 * 2][col] + sQ[wn2 * 2 + 1][col];
        int gc = n0 + wn2 * 32 + col;
        ps[(size_t)by * 256 + gc] = s;
        pq[(size_t)by * 256 + gc] = q;
    }
}

// Merged launch: blocks [0,256) -> branch-2 (K=512), [256,1280) -> branch-1 (K=256).
__global__ __launch_bounds__(256, 2) void gemm_both_kernel(
    const float* __restrict__ A2, const float* __restrict__ A1,
    const float* __restrict__ b2p, const float* __restrict__ b1p,
    float* __restrict__ C2, float* __restrict__ C1)
{
    extern __shared__ char dsm[];
    int b = blockIdx.x;
    if (b < 256) {
        gemm_body<512>(dsm, b & 1, b >> 1, A2, g_W2h, g_W2l, b2p, C2, g_psum2, g_psq2);
    } else {
        b -= 256;
        gemm_body<256>(dsm, b & 1, b >> 1, A1, g_W1h, g_W1l, b1p, C1, g_psum1, g_psq1);
    }
}

// ---------------- BN stats final reduce, both sets in one launch -------------
__global__ __launch_bounds__(128) void colstats_final_all_kernel()
{
    int bc = blockIdx.x, t = threadIdx.x;
    const float* ps; const float* pq; float* mean; float* rstd;
    int nch; float invR; int c;
    if (bc < 256) {
        c = bc; ps = g_psum1; pq = g_psq1; mean = g_mean1; rstd = g_rstd1;
        nch = NQ / 128; invR = 1.f / (float)NQ;
    } else {
        c = bc - 256; ps = g_psum2; pq = g_psq2; mean = g_mean2; rstd = g_rstd2;
        nch = NP / 128; invR = 1.f / (float)NP;
    }
    float s = 0.f, q = 0.f;
    for (int i = t; i < nch; i += 128) { s += ps[i * COUTC + c]; q += pq[i * COUTC + c]; }
    __shared__ float ss[128], sq[128];
    ss[t] = s; sq[t] = q;
    __syncthreads();
    for (int o = 64; o > 0; o >>= 1) {
        if (t < o) { ss[t] += ss[t + o]; sq[t] += sq[t + o]; }
        __syncthreads();
    }
    if (t == 0) {
        float mu = ss[0] * invR;
        float var = sq[0] * invR - mu * mu;
        mean[c] = mu;
        rstd[c] = rsqrtf(var + 1e-5f);
    }
}

// ---------------- grid build ------------------------------------------------
__device__ __forceinline__ int cell_of(float x, float y, float z, int* cx, int* cy, int* cz)
{
    int ix = min(max((int)(x * 16.f), 0), 15);
    int iy = min(max((int)(y * 16.f), 0), 15);
    int iz = min(max((int)(z * 16.f), 0), 15);
    *cx = ix; *cy = iy; *cz = iz;
    return (iz << 8) + (iy << 4) + ix;
}

__global__ void grid_zero_kernel()
{
    int i = blockIdx.x * 256 + threadIdx.x;
    if (i < CB * NCELL) { g_cnt[i] = 0; g_qcnt[i] = 0; }
}

__global__ void count_all_kernel(const float* __restrict__ p2, const float* __restrict__ p1)
{
    int cx, cy, cz;
    if (blockIdx.x < 64) {
        int i = blockIdx.x * 256 + threadIdx.x;
        float x = p2[i * 3], y = p2[i * 3 + 1], z = p2[i * 3 + 2];
        int cell = cell_of(x, y, z, &cx, &cy, &cz);
        atomicAdd(&g_cnt[(i >> 12) * NCELL + cell], 1);
    } else {
        int i = (blockIdx.x - 64) * 256 + threadIdx.x;
        float x = p1[i * 3], y = p1[i * 3 + 1], z = p1[i * 3 + 2];
        int cell = cell_of(x, y, z, &cx, &cy, &cz);
        atomicAdd(&g_qcnt[(i >> 14) * NCELL + cell], 1);
    }
}

__global__ __launch_bounds__(1024) void scan_all_kernel()
{
    __shared__ int ts[1024];
    bool isQ = blockIdx.x >= 4;
    int b = isQ ? blockIdx.x - 4 : blockIdx.x;
    const int* cnt = isQ ? g_qcnt : g_cnt;
    int* ptr = isQ ? g_qptr : g_cellPtr;
    int t = threadIdx.x;
    int v0 = cnt[b * NCELL + t * 4 + 0];
    int v1 = cnt[b * NCELL + t * 4 + 1];
    int v2 = cnt[b * NCELL + t * 4 + 2];
    int v3 = cnt[b * NCELL + t * 4 + 3];
    int loc = v0 + v1 + v2 + v3;
    ts[t] = loc;
    __syncthreads();
    for (int off = 1; off < 1024; off <<= 1) {
        int add = (t >= off) ? ts[t - off] : 0;
        __syncthreads();
        ts[t] += add;
        __syncthreads();
    }
    int p = ts[t] - loc;
    if (!isQ) {
        int base = b * (NCELL + 1);
        g_cellStart[base + t * 4 + 0] = p;
        g_cellStart[base + t * 4 + 1] = p + v0;
        g_cellStart[base + t * 4 + 2] = p + v0 + v1;
        g_cellStart[base + t * 4 + 3] = p + v0 + v1 + v2;
        if (t == 1023) g_cellStart[base + NCELL] = ts[1023];
    }
    ptr[b * NCELL + t * 4 + 0] = p;         p += v0;
    ptr[b * NCELL + t * 4 + 1] = p;         p += v1;
    ptr[b * NCELL + t * 4 + 2] = p;         p += v2;
    ptr[b * NCELL + t * 4 + 3] = p;
}

__global__ void scatter_all_kernel(const float* __restrict__ p2, const float* __restrict__ p1)
{
    int cx, cy, cz;
    if (blockIdx.x < 64) {
        int i = blockIdx.x * 256 + threadIdx.x;
        int b = i >> 12;
        float x = p2[i * 3], y = p2[i * 3 + 1], z = p2[i * 3 + 2];
        float pp = __fadd_rn(__fadd_rn(__fmul_rn(x, x), __fmul_rn(y, y)), __fmul_rn(z, z));
        int cell = cell_of(x, y, z, &cx, &cy, &cz);
        int pos = atomicAdd(&g_cellPtr[b * NCELL + cell], 1);
        g_sortedPts[b * N2C + pos] = make_float4(x, y, z, pp);
        g_sortedIdx[b * N2C + pos] = i;
    } else {
        int i = (blockIdx.x - 64) * 256 + threadIdx.x;
        int b = i >> 14;
        float x = p1[i * 3], y = p1[i * 3 + 1], z = p1[i * 3 + 2];
        float qq = __fadd_rn(__fadd_rn(__fmul_rn(x, x), __fmul_rn(y, y)), __fmul_rn(z, z));
        int cell = cell_of(x, y, z, &cx, &cy, &cz);
        int pos = atomicAdd(&g_qptr[b * NCELL + cell], 1);
        g_sortedQ[b * N1C + pos] = make_float4(x, y, z, qq);
        g_sortedQid[b * N1C + pos] = i;
    }
}

__global__ void grid_sortfix_kernel()
{
    int t = blockIdx.x * 256 + threadIdx.x;
    if (t >= CB * NCELL) return;
    int b = t >> 12, cell = t & 4095;
    int s = g_cellStart[b * (NCELL + 1) + cell];
    int e = g_cellStart[b * (NCELL + 1) + cell + 1];
    int base = b * N2C;
    for (int a = s + 1; a < e; a++) {
        int ia = g_sortedIdx[base + a];
        float4 pa = g_sortedPts[base + a];
        int k = a - 1;
        while (k >= s && g_sortedIdx[base + k] > ia) {
            g_sortedIdx[base + k + 1] = g_sortedIdx[base + k];
            g_sortedPts[base + k + 1] = g_sortedPts[base + k];
            k--;
        }
        g_sortedIdx[base + k + 1] = ia;
        g_sortedPts[base + k + 1] = pa;
    }
}

// ---------------- KNN (K=3): ring expansion with EXACT box-face bound --------
__global__ __launch_bounds__(256) void knn_kernel()
{
    extern __shared__ unsigned char smraw[];
    float4* sp = (float4*)smraw;                                  // 4096 float4
    int* cs  = (int*)(smraw + N2C * sizeof(float4));              // 4097 ints
    int* sid = (int*)(smraw + N2C * sizeof(float4) + (NCELL + 16) * sizeof(int)); // 4096 ints

    int pos = blockIdx.x * 256 + threadIdx.x;
    int batch = pos >> 14;
    for (int i = threadIdx.x; i < N2C; i += 256) {
        sp[i]  = g_sortedPts[batch * N2C + i];
        sid[i] = g_sortedIdx[batch * N2C + i];
    }
    for (int i = threadIdx.x; i < NCELL + 1; i += 256)
        cs[i] = g_cellStart[batch * (NCELL + 1) + i];
    __syncthreads();

    float4 qv = g_sortedQ[pos];
    int qid = g_sortedQid[pos];
    float qx = qv.x, qy = qv.y, qz = qv.z, qq = qv.w;

    int cx, cy, cz;
    (void)cell_of(qx, qy, qz, &cx, &cy, &cz);

    float b0 = 3.4e38f, b1 = 3.4e38f, b2 = 3.4e38f;
    int i0 = 0x7fffffff, i1 = 0x7fffffff, i2 = 0x7fffffff;

    auto proc = [&](int s, int e) {
        for (int j = s; j < e; j++) {
            float4 p = sp[j];
            int oi = sid[j];
            float dot = fmaf(qz, p.z, fmaf(qy, p.y, __fmul_rn(qx, p.x)));
            float d2 = __fsub_rn(__fadd_rn(qq, p.w), __fmul_rn(2.0f, dot));
            bool lt2 = (d2 < b2) || (d2 == b2 && oi < i2);
            if (lt2) {
                bool lt1 = (d2 < b1) || (d2 == b1 && oi < i1);
                if (lt1) {
                    b2 = b1; i2 = i1;
                    bool lt0 = (d2 < b0) || (d2 == b0 && oi < i0);
                    if (lt0) { b1 = b0; i1 = i0; b0 = d2; i0 = oi; }
                    else     { b1 = d2; i1 = oi; }
                } else { b2 = d2; i2 = oi; }
            }
        }
    };

    const float h = 0.0625f;
    for (int r = 0; ; r++) {
        int zlo = max(cz - r, 0), zhi = min(cz + r, 15);
        for (int z = zlo; z <= zhi; z++) {
            bool ze = (z == cz - r) || (z == cz + r);
            int ylo = max(cy - r, 0), yhi = min(cy + r, 15);
            for (int y = ylo; y <= yhi; y++) {
                bool ye = (y == cy - r) || (y == cy + r);
                int rb = (z << 8) + (y << 4);
                if (ze || ye) {
                    int xlo = max(cx - r, 0), xhi = min(cx + r, 15);
                    proc(cs[rb + xlo], cs[rb + xhi + 1]);   // contiguous x-span
                } else {
                    if (cx - r >= 0) proc(cs[rb + cx - r], cs[rb + cx - r + 1]);
                    if (cx + r <= 15) proc(cs[rb + cx + r], cs[rb + cx + r + 1]);
                }
            }
        }
        float bnd = 3.4e38f;
        if (cx - r - 1 >= 0) bnd = fminf(bnd, qx - (float)(cx - r) * h);
        if (cx + r + 1 <= 15) bnd = fminf(bnd, (float)(cx + r + 1) * h - qx);
        if (cy - r - 1 >= 0) bnd = fminf(bnd, qy - (float)(cy - r) * h);
        if (cy + r + 1 <= 15) bnd = fminf(bnd, (float)(cy + r + 1) * h - qy);
        if (cz - r - 1 >= 0) bnd = fminf(bnd, qz - (float)(cz - r) * h);
        if (cz + r + 1 <= 15) bnd = fminf(bnd, (float)(cz + r + 1) * h - qz);
        if (bnd > 3e38f) break;                       // whole grid covered
        if (b2 <= bnd * bnd - 1e-5f) break;           // provably done (with fp slack)
    }

    float d0 = fmaxf(b0, 0.f), d1 = fmaxf(b1, 0.f), d2c = fmaxf(b2, 0.f);
    float r0 = __fdiv_rn(1.0f, __fadd_rn(d0, 1e-8f));
    float r1 = __fdiv_rn(1.0f, __fadd_rn(d1, 1e-8f));
    float r2 = __fdiv_rn(1.0f, __fadd_rn(d2c, 1e-8f));
    float sum = __fadd_rn(__fadd_rn(r0, r1), r2);

    g_knnIdx[qid * 3 + 0] = i0;
    g_knnIdx[qid * 3 + 1] = i1;
    g_knnIdx[qid * 3 + 2] = i2;
    g_knnW[qid * 3 + 0] = __fdiv_rn(r0, sum);
    g_knnW[qid * 3 + 1] = __fdiv_rn(r1, sum);
    g_knnW[qid * 3 + 2] = __fdiv_rn(r2, sum);
}

// ---------------- final: BN+relu both branches, gather, weighted add ---------
#define FROWS 8
__global__ __launch_bounds__(256) void final_kernel(
    float* io,
    const float* __restrict__ ga1, const float* __restrict__ be1,
    const float* __restrict__ ga2, const float* __restrict__ be2)
{
    int row0 = blockIdx.x * FROWS;
    int c4 = (threadIdx.x & 63) * 4;
    int rsub = threadIdx.x >> 6;           // 0..3
    __shared__ int si[FROWS][3];
    __shared__ float sw[FROWS][3];
    if (threadIdx.x < FROWS * 3) {
        si[threadIdx.x / 3][threadIdx.x % 3] = g_knnIdx[row0 * 3 + threadIdx.x];
        sw[threadIdx.x / 3][threadIdx.x % 3] = g_knnW[row0 * 3 + threadIdx.x];
    }
    float4 GA1 = *(const float4*)(ga1 + c4), BE1 = *(const float4*)(be1 + c4);
    float4 GA2 = *(const float4*)(ga2 + c4), BE2 = *(const float4*)(be2 + c4);
    float4 RS1 = *(const float4*)(g_rstd1 + c4), ME1 = *(const float4*)(g_mean1 + c4);
    float4 RS2 = *(const float4*)(g_rstd2 + c4), ME2 = *(const float4*)(g_mean2 + c4);
    float G1x = GA1.x * RS1.x, G1y = GA1.y * RS1.y, G1z = GA1.z * RS1.z, G1w = GA1.w * RS1.w;
    float G2x = GA2.x * RS2.x, G2y = GA2.y * RS2.y, G2z = GA2.z * RS2.z, G2w = GA2.w * RS2.w;
    __syncthreads();

#pragma unroll
    for (int rr = rsub; rr < FROWS; rr += 4) {
        int row = row0 + rr;
        float4 x = *(float4*)(io + (size_t)row * COUTC + c4);
        float vx = fmaxf(G1x * (x.x - ME1.x) + BE1.x, 0.f);
        float vy = fmaxf(G1y * (x.y - ME1.y) + BE1.y, 0.f);
        float vz = fmaxf(G1z * (x.z - ME1.z) + BE1.z, 0.f);
        float vw = fmaxf(G1w * (x.w - ME1.w) + BE1.w, 0.f);
        float ax = 0.f, ay = 0.f, az = 0.f, aw = 0.f;
#pragma unroll
        for (int k = 0; k < 3; k++) {
            float4 y = *(const float4*)(g_f2pre + (size_t)si[rr][k] * COUTC + c4);
            float w = sw[rr][k];
            ax = fmaf(w, fmaxf(G2x * (y.x - ME2.x) + BE2.x, 0.f), ax);
            ay = fmaf(w, fmaxf(G2y * (y.y - ME2.y) + BE2.y, 0.f), ay);
            az = fmaf(w, fmaxf(G2z * (y.z - ME2.z) + BE2.z, 0.f), az);
            aw = fmaf(w, fmaxf(G2w * (y.w - ME2.w) + BE2.w, 0.f), aw);
        }
        float4 o;
        o.x = vx + ax; o.y = vy + ay; o.z = vz + az; o.w = vw + aw;
        *(float4*)(io + (size_t)row * COUTC + c4) = o;
    }
}

// ---------------- launch ----------------------------------------------------
extern "C" void kernel_launch(void* const* d_in, const int* in_sizes, int n_in,
                              void* d_out, int out_size)
{
    const float* p1  = (const float*)d_in[0];
    const float* f1  = (const float*)d_in[1];
    const float* p2  = (const float*)d_in[2];
    const float* f2  = (const float*)d_in[3];
    const float* W1  = (const float*)d_in[4];
    const float* b1  = (const float*)d_in[5];
    const float* ga1 = (const float*)d_in[6];
    const float* be1 = (const float*)d_in[7];
    const float* W2  = (const float*)d_in[8];
    const float* b2  = (const float*)d_in[9];
    const float* ga2 = (const float*)d_in[10];
    const float* be2 = (const float*)d_in[11];
    float* out = (float*)d_out;

    float *f2pre;
    cudaGetSymbolAddress((void**)&f2pre, g_f2pre);

    // fork/join: chain B (grid+KNN) runs on side stream, overlapping the GEMMs
    cudaStream_t s2;
    cudaEvent_t eFork, eJoin;
    cudaStreamCreateWithFlags(&s2, cudaStreamNonBlocking);
    cudaEventCreateWithFlags(&eFork, cudaEventDisableTiming);
    cudaEventCreateWithFlags(&eJoin, cudaEventDisableTiming);

    size_t sm = N2C * sizeof(float4) + (NCELL + 16) * sizeof(int) + N2C * sizeof(int);
    cudaFuncSetAttribute(knn_kernel, cudaFuncAttributeMaxDynamicSharedMemorySize, (int)sm);
    cudaFuncSetAttribute(gemm_both_kernel, cudaFuncAttributeMaxDynamicSharedMemorySize, DB_TOTAL);

    // fork
    cudaEventRecord(eFork, 0);
    cudaStreamWaitEvent(s2, eFork, 0);

    // chain B (side stream): spatial grids + KNN
    grid_zero_kernel<<<64, 256, 0, s2>>>();
    count_all_kernel<<<320, 256, 0, s2>>>(p2, p1);
    scan_all_kernel<<<8, 1024, 0, s2>>>();
    scatter_all_kernel<<<320, 256, 0, s2>>>(p2, p1);
    grid_sortfix_kernel<<<64, 256, 0, s2>>>();
    knn_kernel<<<256, 256, sm, s2>>>();
    cudaEventRecord(eJoin, s2);

    // chain A (main stream): weight split + merged GEMM + BN stats
    wt_split_all_kernel<<<768, 256>>>(W1, W2);
    gemm_both_kernel<<<256 + 1024, 256, DB_TOTAL>>>(f2, f1, b2, b1, f2pre, out);
    colstats_final_all_kernel<<<512, 128>>>();

    // join + fused epilogue
    cudaStreamWaitEvent(0, eJoin, 0);
    final_kernel<<<NQ / FROWS, 256>>>(out, ga1, be1, ga2, be2);
}

// round 14
// speedup vs baseline: 1.0246x; 1.0246x over previous
#include <cuda_runtime.h>
#include <cuda_bf16.h>
#include <cstdint>

// Problem constants
#define CB      4          // batches
#define N1C     16384      // queries per batch
#define N2C     4096       // points per batch
#define NQ      (CB*N1C)   // 65536
#define NP      (CB*N2C)   // 16384
#define COUTC   256
#define GRIDG   16
#define NCELL   (GRIDG*GRIDG*GRIDG)  // 4096

__device__ __forceinline__ uint32_t smem_to_u32(const void* smem_ptr) {
    uint32_t addr;
    asm("{ .reg .u64 tmp; cvta.to.shared.u64 tmp, %1; cvt.u32.u64 %0, tmp; }"
        : "=r"(addr) : "l"(smem_ptr));
    return addr;
}
__device__ __forceinline__ void ldm_x4(uint32_t* r, uint32_t addr) {
    asm volatile("ldmatrix.sync.aligned.m8n8.x4.shared.b16 {%0,%1,%2,%3}, [%4];"
        : "=r"(r[0]), "=r"(r[1]), "=r"(r[2]), "=r"(r[3]) : "r"(addr));
}
__device__ __forceinline__ void ldm_x2(uint32_t* r, uint32_t addr) {
    asm volatile("ldmatrix.sync.aligned.m8n8.x2.shared.b16 {%0,%1}, [%2];"
        : "=r"(r[0]), "=r"(r[1]) : "r"(addr));
}
__device__ __forceinline__ void mma_bf16(float* c, const uint32_t* a, const uint32_t* b) {
    asm volatile("mma.sync.aligned.m16n8k16.row.col.f32.bf16.bf16.f32 "
        "{%0,%1,%2,%3}, {%4,%5,%6,%7}, {%8,%9}, {%0,%1,%2,%3};"
        : "+f"(c[0]), "+f"(c[1]), "+f"(c[2]), "+f"(c[3])
        : "r"(a[0]), "r"(a[1]), "r"(a[2]), "r"(a[3]), "r"(b[0]), "r"(b[1]));
}
__device__ __forceinline__ void cp_async16(uint32_t dst, const void* src) {
    asm volatile("cp.async.cg.shared.global [%0], [%1], 16;" :: "r"(dst), "l"(src));
}
#define CP_COMMIT() asm volatile("cp.async.commit_group;" ::: "memory")
#define CP_WAIT0()  asm volatile("cp.async.wait_group 0;" ::: "memory")

__device__ __forceinline__ uint32_t pack_bf2(__nv_bfloat16 a, __nv_bfloat16 b) {
    __nv_bfloat162 t(a, b);
    return *reinterpret_cast<uint32_t*>(&t);
}

// ---------------- device scratch (static — no allocation allowed) ------------
__device__ float  g_f2pre[NP * COUTC];         // 16 MB pre-activation of branch 2
__device__ __nv_bfloat16 g_W1h[256 * 256];     // transposed [N][K]
__device__ __nv_bfloat16 g_W1l[256 * 256];
__device__ __nv_bfloat16 g_W2h[256 * 512];
__device__ __nv_bfloat16 g_W2l[256 * 512];
__device__ float  g_psum1[512 * COUTC];
__device__ float  g_psq1 [512 * COUTC];
__device__ float  g_psum2[128 * COUTC];
__device__ float  g_psq2 [128 * COUTC];
__device__ float  g_mean1[COUTC], g_rstd1[COUTC];
__device__ float  g_mean2[COUTC], g_rstd2[COUTC];
__device__ int    g_cnt[CB * NCELL];
__device__ int    g_cellStart[CB * (NCELL + 1)];
__device__ int    g_cellPtr[CB * NCELL];
__device__ float4 g_sortedPts[CB * N2C];       // x,y,z,|p|^2  (cell-sorted)
__device__ int    g_sortedIdx[CB * N2C];       // original row index (global)
__device__ int    g_qcnt[CB * NCELL];
__device__ int    g_qptr[CB * NCELL];
__device__ float4 g_sortedQ[NQ];               // x,y,z,|q|^2  (cell-sorted queries)
__device__ int    g_sortedQid[NQ];
__device__ int    g_knnIdx[NQ * 3];
__device__ float  g_knnW [NQ * 3];

// Both weight transposes + hi/lo splits in one launch.
__global__ __launch_bounds__(256) void wt_split_all_kernel(
    const float* __restrict__ W1, const float* __restrict__ W2)
{
    int i = blockIdx.x * 256 + threadIdx.x;
    if (i < 256 * 256) {
        int k = i >> 8, n = i & 255;
        float x = W1[i];
        __nv_bfloat16 h = __float2bfloat16_rn(x);
        g_W1h[n * 256 + k] = h;
        g_W1l[n * 256 + k] = __float2bfloat16_rn(x - __bfloat162float(h));
    } else {
        int j = i - 256 * 256;
        if (j >= 512 * 256) return;
        int k = j >> 8, n = j & 255;
        float x = W2[j];
        __nv_bfloat16 h = __float2bfloat16_rn(x);
        g_W2h[n * 512 + k] = h;
        g_W2l[n * 512 + k] = __float2bfloat16_rn(x - __bfloat162float(h));
    }
}

// ---------------- mma.sync bf16x3 GEMM: double-buffered pipeline -------------
#define PITCH 40                    // bf16 per smem row (80B — conflict-free ldmatrix)
#define TILEB 10240                 // one 128xPITCH bf16 tile in bytes
#define DB_AH 0
#define DB_AL TILEB
#define DB_BH (2*TILEB)
#define DB_BL (3*TILEB)
#define DB_BUF (4*TILEB)            // bytes per buffer (40960)
#define DB_S   (8*TILEB)            // sS after both buffers
#define DB_Q   (8*TILEB + 1024)
#define DB_TOTAL (8*TILEB + 2048)   // 83968 bytes

template<int K>
__global__ __launch_bounds__(256, 2) void gemm_mma_kernel(
    const float* __restrict__ A,
    const __nv_bfloat16* __restrict__ Bh, const __nv_bfloat16* __restrict__ Bl,
    const float* __restrict__ bias, float* __restrict__ C,
    float* __restrict__ ps, float* __restrict__ pq)
{
    extern __shared__ char dsm[];
    const uint32_t base = smem_to_u32(dsm);
    float (*sS)[32] = (float(*)[32])(dsm + DB_S);
    float (*sQ)[32] = (float(*)[32])(dsm + DB_Q);

    const int tid = threadIdx.x, lane = tid & 31, wid = tid >> 5;
    const int wm = wid & 1, wn = wid >> 1;      // warp grid: 2 (m) x 4 (n)
    const int m0 = blockIdx.y * 128, n0 = blockIdx.x * 128;

    float acc[4][4][4];
#pragma unroll
    for (int i = 0; i < 4; i++)
#pragma unroll
        for (int j = 0; j < 4; j++)
#pragma unroll
            for (int k = 0; k < 4; k++) acc[i][j][k] = 0.f;

    const uint32_t aoff = ((uint32_t)((wm * 64 + (lane & 15)) * PITCH + (lane >> 4) * 8)) * 2;
    const uint32_t boff = ((uint32_t)((wn * 32 + (lane & 7)) * PITCH + ((lane >> 3) & 1) * 8)) * 2;

    float4 ra[4];   // A stage regs (held across compute in steady state)

    auto issueB = [&](int kt, int buf) {
        uint32_t dbh = base + buf * DB_BUF + DB_BH;
        uint32_t dbl = base + buf * DB_BUF + DB_BL;
        int k0 = kt * 32;
#pragma unroll
        for (int i = 0; i < 2; i++) {
            int fid = i * 256 + tid, r = fid >> 2, q = fid & 3;
            size_t gb = (size_t)(n0 + r) * K + k0 + q * 8;
            uint32_t so = (uint32_t)(r * PITCH + q * 8) * 2;
            cp_async16(dbh + so, Bh + gb);
            cp_async16(dbl + so, Bl + gb);
        }
        CP_COMMIT();
    };
    auto loadA = [&](int kt) {
        int k0 = kt * 32;
#pragma unroll
        for (int i = 0; i < 4; i++) {
            int fid = i * 256 + tid, r = fid >> 3, q = fid & 7;
            ra[i] = *(const float4*)(A + (size_t)(m0 + r) * K + k0 + q * 4);
        }
    };
    auto storeA = [&](int buf) {
        __nv_bfloat16* sAh = (__nv_bfloat16*)(dsm + buf * DB_BUF + DB_AH);
        __nv_bfloat16* sAl = (__nv_bfloat16*)(dsm + buf * DB_BUF + DB_AL);
#pragma unroll
        for (int i = 0; i < 4; i++) {
            int fid = i * 256 + tid, r = fid >> 3, q = fid & 7;
            float4 v = ra[i];
            __nv_bfloat16 h0 = __float2bfloat16_rn(v.x);
            __nv_bfloat16 h1 = __float2bfloat16_rn(v.y);
            __nv_bfloat16 h2 = __float2bfloat16_rn(v.z);
            __nv_bfloat16 h3 = __float2bfloat16_rn(v.w);
            __nv_bfloat16 l0 = __float2bfloat16_rn(v.x - __bfloat162float(h0));
            __nv_bfloat16 l1 = __float2bfloat16_rn(v.y - __bfloat162float(h1));
            __nv_bfloat16 l2 = __float2bfloat16_rn(v.z - __bfloat162float(h2));
            __nv_bfloat16 l3 = __float2bfloat16_rn(v.w - __bfloat162float(h3));
            int so = r * PITCH + q * 4;
            uint2 ph, pl;
            ph.x = pack_bf2(h0, h1); ph.y = pack_bf2(h2, h3);
            pl.x = pack_bf2(l0, l1); pl.y = pack_bf2(l2, l3);
            *(uint2*)(sAh + so) = ph;
            *(uint2*)(sAl + so) = pl;
        }
    };
    auto compute = [&](int buf) {
        uint32_t uAh = base + buf * DB_BUF + DB_AH;
        uint32_t uAl = base + buf * DB_BUF + DB_AL;
        uint32_t uBh = base + buf * DB_BUF + DB_BH;
        uint32_t uBl = base + buf * DB_BUF + DB_BL;
#pragma unroll
        for (int ks = 0; ks < 2; ks++) {
            uint32_t bfh[4][2], bfl[4][2];
#pragma unroll
            for (int nt = 0; nt < 4; nt++) {
                uint32_t o = boff + (uint32_t)(nt * 8 * PITCH + ks * 16) * 2;
                ldm_x2(bfh[nt], uBh + o);
                ldm_x2(bfl[nt], uBl + o);
            }
#pragma unroll
            for (int mt = 0; mt < 4; mt++) {
                uint32_t afh[4], afl[4];
                uint32_t o = aoff + (uint32_t)(mt * 16 * PITCH + ks * 16) * 2;
                ldm_x4(afh, uAh + o);
                ldm_x4(afl, uAl + o);
#pragma unroll
                for (int nt = 0; nt < 4; nt++) {
                    mma_bf16(acc[mt][nt], afh, bfh[nt]);
                    mma_bf16(acc[mt][nt], afh, bfl[nt]);
                    mma_bf16(acc[mt][nt], afl, bfh[nt]);
                }
            }
        }
    };

    const int NIT = K / 32;
    issueB(0, 0);
    loadA(0);
    storeA(0);
    CP_WAIT0();
    __syncthreads();

    for (int kt = 0; kt < NIT; kt++) {
        int cur = kt & 1, nxt = cur ^ 1;
        if (kt + 1 < NIT) {
            issueB(kt + 1, nxt);   // cp.async — overlaps compute below
            loadA(kt + 1);         // LDGs in flight across compute
        }
        compute(cur);
        if (kt + 1 < NIT) {
            storeA(nxt);           // convert + store into alternate buffer
            CP_WAIT0();
        }
        __syncthreads();
    }

    // epilogue: bias add, store C, per-block column sum/sumsq
    const int tr = lane >> 2, tc = (lane & 3) * 2;
    const int rbase = m0 + wm * 64, cbase = n0 + wn * 32;
#pragma unroll
    for (int nt = 0; nt < 4; nt++) {
        int col = cbase + nt * 8 + tc;
        float bx = bias[col], by = bias[col + 1];
        float s0 = 0.f, s1 = 0.f, q0 = 0.f, q1 = 0.f;
#pragma unroll
        for (int mt = 0; mt < 4; mt++) {
            int row = rbase + mt * 16 + tr;
            float v0 = acc[mt][nt][0] + bx, v1 = acc[mt][nt][1] + by;
            float v2 = acc[mt][nt][2] + bx, v3 = acc[mt][nt][3] + by;
            *(float2*)(C + (size_t)row * 256 + col) = make_float2(v0, v1);
            *(float2*)(C + (size_t)(row + 8) * 256 + col) = make_float2(v2, v3);
            s0 += v0 + v2; s1 += v1 + v3;
            q0 = fmaf(v0, v0, q0); q0 = fmaf(v2, v2, q0);
            q1 = fmaf(v1, v1, q1); q1 = fmaf(v3, v3, q1);
        }
#pragma unroll
        for (int off = 4; off <= 16; off <<= 1) {
            s0 += __shfl_xor_sync(0xffffffff, s0, off);
            s1 += __shfl_xor_sync(0xffffffff, s1, off);
            q0 += __shfl_xor_sync(0xffffffff, q0, off);
            q1 += __shfl_xor_sync(0xffffffff, q1, off);
        }
        if (tr == 0) {
            int lc = nt * 8 + tc;
            sS[wid][lc] = s0; sS[wid][lc + 1] = s1;
            sQ[wid][lc] = q0; sQ[wid][lc + 1] = q1;
        }
    }
    __syncthreads();
    if (tid < 128) {
        int wn2 = tid >> 5, col = tid & 31;
        float s = sS[wn2 * 2][col] + sS[wn2 * 2 + 1][col];
        float q = sQ[wn2 * 2][col] + sQ[wn2 * 2 + 1][col];
        int gc = n0 + wn2 * 32 + col;
        ps[(size_t)blockIdx.y * 256 + gc] = s;
        pq[(size_t)blockIdx.y * 256 + gc] = q;
    }
}

// ---------------- BN stats final reduce, both sets in one launch -------------
__global__ __launch_bounds__(128) void colstats_final_all_kernel()
{
    int bc = blockIdx.x, t = threadIdx.x;
    const float* ps; const float* pq; float* mean; float* rstd;
    int nch; float invR; int c;
    if (bc < 256) {
        c = bc; ps = g_psum1; pq = g_psq1; mean = g_mean1; rstd = g_rstd1;
        nch = NQ / 128; invR = 1.f / (float)NQ;
    } else {
        c = bc - 256; ps = g_psum2; pq = g_psq2; mean = g_mean2; rstd = g_rstd2;
        nch = NP / 128; invR = 1.f / (float)NP;
    }
    float s = 0.f, q = 0.f;
    for (int i = t; i < nch; i += 128) { s += ps[i * COUTC + c]; q += pq[i * COUTC + c]; }
    __shared__ float ss[128], sq[128];
    ss[t] = s; sq[t] = q;
    __syncthreads();
    for (int o = 64; o > 0; o >>= 1) {
        if (t < o) { ss[t] += ss[t + o]; sq[t] += sq[t + o]; }
        __syncthreads();
    }
    if (t == 0) {
        float mu = ss[0] * invR;
        float var = sq[0] * invR - mu * mu;
        mean[c] = mu;
        rstd[c] = rsqrtf(var + 1e-5f);
    }
}

// ---------------- grid build ------------------------------------------------
__device__ __forceinline__ int cell_of(float x, float y, float z, int* cx, int* cy, int* cz)
{
    int ix = min(max((int)(x * 16.f), 0), 15);
    int iy = min(max((int)(y * 16.f), 0), 15);
    int iz = min(max((int)(z * 16.f), 0), 15);
    *cx = ix; *cy = iy; *cz = iz;
    return (iz << 8) + (iy << 4) + ix;
}

__global__ void grid_zero_kernel()
{
    int i = blockIdx.x * 256 + threadIdx.x;
    if (i < CB * NCELL) { g_cnt[i] = 0; g_qcnt[i] = 0; }
}

__global__ void count_all_kernel(const float* __restrict__ p2, const float* __restrict__ p1)
{
    int cx, cy, cz;
    if (blockIdx.x < 64) {
        int i = blockIdx.x * 256 + threadIdx.x;
        float x = p2[i * 3], y = p2[i * 3 + 1], z = p2[i * 3 + 2];
        int cell = cell_of(x, y, z, &cx, &cy, &cz);
        atomicAdd(&g_cnt[(i >> 12) * NCELL + cell], 1);
    } else {
        int i = (blockIdx.x - 64) * 256 + threadIdx.x;
        float x = p1[i * 3], y = p1[i * 3 + 1], z = p1[i * 3 + 2];
        int cell = cell_of(x, y, z, &cx, &cy, &cz);
        atomicAdd(&g_qcnt[(i >> 14) * NCELL + cell], 1);
    }
}

__global__ __launch_bounds__(1024) void scan_all_kernel()
{
    __shared__ int ts[1024];
    bool isQ = blockIdx.x >= 4;
    int b = isQ ? blockIdx.x - 4 : blockIdx.x;
    const int* cnt = isQ ? g_qcnt : g_cnt;
    int* ptr = isQ ? g_qptr : g_cellPtr;
    int t = threadIdx.x;
    int v0 = cnt[b * NCELL + t * 4 + 0];
    int v1 = cnt[b * NCELL + t * 4 + 1];
    int v2 = cnt[b * NCELL + t * 4 + 2];
    int v3 = cnt[b * NCELL + t * 4 + 3];
    int loc = v0 + v1 + v2 + v3;
    ts[t] = loc;
    __syncthreads();
    for (int off = 1; off < 1024; off <<= 1) {
        int add = (t >= off) ? ts[t - off] : 0;
        __syncthreads();
        ts[t] += add;
        __syncthreads();
    }
    int p = ts[t] - loc;
    if (!isQ) {
        int base = b * (NCELL + 1);
        g_cellStart[base + t * 4 + 0] = p;
        g_cellStart[base + t * 4 + 1] = p + v0;
        g_cellStart[base + t * 4 + 2] = p + v0 + v1;
        g_cellStart[base + t * 4 + 3] = p + v0 + v1 + v2;
        if (t == 1023) g_cellStart[base + NCELL] = ts[1023];
    }
    ptr[b * NCELL + t * 4 + 0] = p;         p += v0;
    ptr[b * NCELL + t * 4 + 1] = p;         p += v1;
    ptr[b * NCELL + t * 4 + 2] = p;         p += v2;
    ptr[b * NCELL + t * 4 + 3] = p;
}

__global__ void scatter_all_kernel(const float* __restrict__ p2, const float* __restrict__ p1)
{
    int cx, cy, cz;
    if (blockIdx.x < 64) {
        int i = blockIdx.x * 256 + threadIdx.x;
        int b = i >> 12;
        float x = p2[i * 3], y = p2[i * 3 + 1], z = p2[i * 3 + 2];
        float pp = __fadd_rn(__fadd_rn(__fmul_rn(x, x), __fmul_rn(y, y)), __fmul_rn(z, z));
        int cell = cell_of(x, y, z, &cx, &cy, &cz);
        int pos = atomicAdd(&g_cellPtr[b * NCELL + cell], 1);
        g_sortedPts[b * N2C + pos] = make_float4(x, y, z, pp);
        g_sortedIdx[b * N2C + pos] = i;
    } else {
        int i = (blockIdx.x - 64) * 256 + threadIdx.x;
        int b = i >> 14;
        float x = p1[i * 3], y = p1[i * 3 + 1], z = p1[i * 3 + 2];
        float qq = __fadd_rn(__fadd_rn(__fmul_rn(x, x), __fmul_rn(y, y)), __fmul_rn(z, z));
        int cell = cell_of(x, y, z, &cx, &cy, &cz);
        int pos = atomicAdd(&g_qptr[b * NCELL + cell], 1);
        g_sortedQ[b * N1C + pos] = make_float4(x, y, z, qq);
        g_sortedQid[b * N1C + pos] = i;
    }
}

__global__ void grid_sortfix_kernel()
{
    int t = blockIdx.x * 256 + threadIdx.x;
    if (t >= CB * NCELL) return;
    int b = t >> 12, cell = t & 4095;
    int s = g_cellStart[b * (NCELL + 1) + cell];
    int e = g_cellStart[b * (NCELL + 1) + cell + 1];
    int base = b * N2C;
    for (int a = s + 1; a < e; a++) {
        int ia = g_sortedIdx[base + a];
        float4 pa = g_sortedPts[base + a];
        int k = a - 1;
        while (k >= s && g_sortedIdx[base + k] > ia) {
            g_sortedIdx[base + k + 1] = g_sortedIdx[base + k];
            g_sortedPts[base + k + 1] = g_sortedPts[base + k];
            k--;
        }
        g_sortedIdx[base + k + 1] = ia;
        g_sortedPts[base + k + 1] = pa;
    }
}

// ---------------- KNN (K=3): ring expansion with EXACT box-face bound --------
__global__ __launch_bounds__(256) void knn_kernel()
{
    extern __shared__ unsigned char smraw[];
    float4* sp = (float4*)smraw;                                  // 4096 float4
    int* cs  = (int*)(smraw + N2C * sizeof(float4));              // 4097 ints
    int* sid = (int*)(smraw + N2C * sizeof(float4) + (NCELL + 16) * sizeof(int)); // 4096 ints

    int pos = blockIdx.x * 256 + threadIdx.x;
    int batch = pos >> 14;
    for (int i = threadIdx.x; i < N2C; i += 256) {
        sp[i]  = g_sortedPts[batch * N2C + i];
        sid[i] = g_sortedIdx[batch * N2C + i];
    }
    for (int i = threadIdx.x; i < NCELL + 1; i += 256)
        cs[i] = g_cellStart[batch * (NCELL + 1) + i];
    __syncthreads();

    float4 qv = g_sortedQ[pos];
    int qid = g_sortedQid[pos];
    float qx = qv.x, qy = qv.y, qz = qv.z, qq = qv.w;

    int cx, cy, cz;
    (void)cell_of(qx, qy, qz, &cx, &cy, &cz);

    float b0 = 3.4e38f, b1 = 3.4e38f, b2 = 3.4e38f;
    int i0 = 0x7fffffff, i1 = 0x7fffffff, i2 = 0x7fffffff;

    auto proc = [&](int s, int e) {
        for (int j = s; j < e; j++) {
            float4 p = sp[j];
            int oi = sid[j];
            float dot = fmaf(qz, p.z, fmaf(qy, p.y, __fmul_rn(qx, p.x)));
            float d2 = __fsub_rn(__fadd_rn(qq, p.w), __fmul_rn(2.0f, dot));
            bool lt2 = (d2 < b2) || (d2 == b2 && oi < i2);
            if (lt2) {
                bool lt1 = (d2 < b1) || (d2 == b1 && oi < i1);
                if (lt1) {
                    b2 = b1; i2 = i1;
                    bool lt0 = (d2 < b0) || (d2 == b0 && oi < i0);
                    if (lt0) { b1 = b0; i1 = i0; b0 = d2; i0 = oi; }
                    else     { b1 = d2; i1 = oi; }
                } else { b2 = d2; i2 = oi; }
            }
        }
    };

    const float h = 0.0625f;
    for (int r = 0; ; r++) {
        int zlo = max(cz - r, 0), zhi = min(cz + r, 15);
        for (int z = zlo; z <= zhi; z++) {
            bool ze = (z == cz - r) || (z == cz + r);
            int ylo = max(cy - r, 0), yhi = min(cy + r, 15);
            for (int y = ylo; y <= yhi; y++) {
                bool ye = (y == cy - r) || (y == cy + r);
                int rb = (z << 8) + (y << 4);
                if (ze || ye) {
                    int xlo = max(cx - r, 0), xhi = min(cx + r, 15);
                    proc(cs[rb + xlo], cs[rb + xhi + 1]);   // contiguous x-span
                } else {
                    if (cx - r >= 0) proc(cs[rb + cx - r], cs[rb + cx - r + 1]);
                    if (cx + r <= 15) proc(cs[rb + cx + r], cs[rb + cx + r + 1]);
                }
            }
        }
        float bnd = 3.4e38f;
        if (cx - r - 1 >= 0) bnd = fminf(bnd, qx - (float)(cx - r) * h);
        if (cx + r + 1 <= 15) bnd = fminf(bnd, (float)(cx + r + 1) * h - qx);
        if (cy - r - 1 >= 0) bnd = fminf(bnd, qy - (float)(cy - r) * h);
        if (cy + r + 1 <= 15) bnd = fminf(bnd, (float)(cy + r + 1) * h - qy);
        if (cz - r - 1 >= 0) bnd = fminf(bnd, qz - (float)(cz - r) * h);
        if (cz + r + 1 <= 15) bnd = fminf(bnd, (float)(cz + r + 1) * h - qz);
        if (bnd > 3e38f) break;                       // whole grid covered
        if (b2 <= bnd * bnd - 1e-5f) break;           // provably done (with fp slack)
    }

    float d0 = fmaxf(b0, 0.f), d1 = fmaxf(b1, 0.f), d2c = fmaxf(b2, 0.f);
    float r0 = __fdiv_rn(1.0f, __fadd_rn(d0, 1e-8f));
    float r1 = __fdiv_rn(1.0f, __fadd_rn(d1, 1e-8f));
    float r2 = __fdiv_rn(1.0f, __fadd_rn(d2c, 1e-8f));
    float sum = __fadd_rn(__fadd_rn(r0, r1), r2);

    g_knnIdx[qid * 3 + 0] = i0;
    g_knnIdx[qid * 3 + 1] = i1;
    g_knnIdx[qid * 3 + 2] = i2;
    g_knnW[qid * 3 + 0] = __fdiv_rn(r0, sum);
    g_knnW[qid * 3 + 1] = __fdiv_rn(r1, sum);
    g_knnW[qid * 3 + 2] = __fdiv_rn(r2, sum);
}

// ---------------- final: BN+relu both branches, gather, weighted add ---------
#define FROWS 8
__global__ __launch_bounds__(256) void final_kernel(
    float* io,
    const float* __restrict__ ga1, const float* __restrict__ be1,
    const float* __restrict__ ga2, const float* __restrict__ be2)
{
    int row0 = blockIdx.x * FROWS;
    int c4 = (threadIdx.x & 63) * 4;
    int rsub = threadIdx.x >> 6;           // 0..3
    __shared__ int si[FROWS][3];
    __shared__ float sw[FROWS][3];
    if (threadIdx.x < FROWS * 3) {
        si[threadIdx.x / 3][threadIdx.x % 3] = g_knnIdx[row0 * 3 + threadIdx.x];
        sw[threadIdx.x / 3][threadIdx.x % 3] = g_knnW[row0 * 3 + threadIdx.x];
    }
    float4 GA1 = *(const float4*)(ga1 + c4), BE1 = *(const float4*)(be1 + c4);
    float4 GA2 = *(const float4*)(ga2 + c4), BE2 = *(const float4*)(be2 + c4);
    float4 RS1 = *(const float4*)(g_rstd1 + c4), ME1 = *(const float4*)(g_mean1 + c4);
    float4 RS2 = *(const float4*)(g_rstd2 + c4), ME2 = *(const float4*)(g_mean2 + c4);
    float G1x = GA1.x * RS1.x, G1y = GA1.y * RS1.y, G1z = GA1.z * RS1.z, G1w = GA1.w * RS1.w;
    float G2x = GA2.x * RS2.x, G2y = GA2.y * RS2.y, G2z = GA2.z * RS2.z, G2w = GA2.w * RS2.w;
    __syncthreads();

#pragma unroll
    for (int rr = rsub; rr < FROWS; rr += 4) {
        int row = row0 + rr;
        float4 x = *(float4*)(io + (size_t)row * COUTC + c4);
        float vx = fmaxf(G1x * (x.x - ME1.x) + BE1.x, 0.f);
        float vy = fmaxf(G1y * (x.y - ME1.y) + BE1.y, 0.f);
        float vz = fmaxf(G1z * (x.z - ME1.z) + BE1.z, 0.f);
        float vw = fmaxf(G1w * (x.w - ME1.w) + BE1.w, 0.f);
        float ax = 0.f, ay = 0.f, az = 0.f, aw = 0.f;
#pragma unroll
        for (int k = 0; k < 3; k++) {
            float4 y = *(const float4*)(g_f2pre + (size_t)si[rr][k] * COUTC + c4);
            float w = sw[rr][k];
            ax = fmaf(w, fmaxf(G2x * (y.x - ME2.x) + BE2.x, 0.f), ax);
            ay = fmaf(w, fmaxf(G2y * (y.y - ME2.y) + BE2.y, 0.f), ay);
            az = fmaf(w, fmaxf(G2z * (y.z - ME2.z) + BE2.z, 0.f), az);
            aw = fmaf(w, fmaxf(G2w * (y.w - ME2.w) + BE2.w, 0.f), aw);
        }
        float4 o;
        o.x = vx + ax; o.y = vy + ay; o.z = vz + az; o.w = vw + aw;
        *(float4*)(io + (size_t)row * COUTC + c4) = o;
    }
}

// ---------------- launch ----------------------------------------------------
extern "C" void kernel_launch(void* const* d_in, const int* in_sizes, int n_in,
                              void* d_out, int out_size)
{
    const float* p1  = (const float*)d_in[0];
    const float* f1  = (const float*)d_in[1];
    const float* p2  = (const float*)d_in[2];
    const float* f2  = (const float*)d_in[3];
    const float* W1  = (const float*)d_in[4];
    const float* b1  = (const float*)d_in[5];
    const float* ga1 = (const float*)d_in[6];
    const float* be1 = (const float*)d_in[7];
    const float* W2  = (const float*)d_in[8];
    const float* b2  = (const float*)d_in[9];
    const float* ga2 = (const float*)d_in[10];
    const float* be2 = (const float*)d_in[11];
    float* out = (float*)d_out;

    float *f2pre, *ps1, *pq1, *ps2, *pq2;
    __nv_bfloat16 *w1h, *w1l, *w2h, *w2l;
    cudaGetSymbolAddress((void**)&f2pre, g_f2pre);
    cudaGetSymbolAddress((void**)&ps1, g_psum1);
    cudaGetSymbolAddress((void**)&pq1, g_psq1);
    cudaGetSymbolAddress((void**)&ps2, g_psum2);
    cudaGetSymbolAddress((void**)&pq2, g_psq2);
    cudaGetSymbolAddress((void**)&w1h, g_W1h);
    cudaGetSymbolAddress((void**)&w1l, g_W1l);
    cudaGetSymbolAddress((void**)&w2h, g_W2h);
    cudaGetSymbolAddress((void**)&w2l, g_W2l);

    // fork/join: chain B (grid+KNN) on a HIGH-PRIORITY side stream so it
    // finishes fully inside the GEMM shadow.
    int prLo, prHi;
    cudaDeviceGetStreamPriorityRange(&prLo, &prHi);
    cudaStream_t s2;
    cudaEvent_t eFork, eJoin;
    cudaStreamCreateWithPriority(&s2, cudaStreamNonBlocking, prHi);
    cudaEventCreateWithFlags(&eFork, cudaEventDisableTiming);
    cudaEventCreateWithFlags(&eJoin, cudaEventDisableTiming);

    size_t sm = N2C * sizeof(float4) + (NCELL + 16) * sizeof(int) + N2C * sizeof(int);
    cudaFuncSetAttribute(knn_kernel, cudaFuncAttributeMaxDynamicSharedMemorySize, (int)sm);
    cudaFuncSetAttribute(gemm_mma_kernel<256>, cudaFuncAttributeMaxDynamicSharedMemorySize, DB_TOTAL);
    cudaFuncSetAttribute(gemm_mma_kernel<512>, cudaFuncAttributeMaxDynamicSharedMemorySize, DB_TOTAL);

    // fork
    cudaEventRecord(eFork, 0);
    cudaStreamWaitEvent(s2, eFork, 0);

    // chain B (side stream): spatial grids + KNN
    grid_zero_kernel<<<64, 256, 0, s2>>>();
    count_all_kernel<<<320, 256, 0, s2>>>(p2, p1);
    scan_all_kernel<<<8, 1024, 0, s2>>>();
    scatter_all_kernel<<<320, 256, 0, s2>>>(p2, p1);
    grid_sortfix_kernel<<<64, 256, 0, s2>>>();
    knn_kernel<<<256, 256, sm, s2>>>();
    cudaEventRecord(eJoin, s2);

    // chain A (main stream): weight split + GEMMs + BN stats
    wt_split_all_kernel<<<768, 256>>>(W1, W2);
    gemm_mma_kernel<512><<<dim3(2, NP / 128), 256, DB_TOTAL>>>(f2, w2h, w2l, b2, f2pre, ps2, pq2);
    gemm_mma_kernel<256><<<dim3(2, NQ / 128), 256, DB_TOTAL>>>(f1, w1h, w1l, b1, out, ps1, pq1);
    colstats_final_all_kernel<<<512, 128>>>();

    // join + fused epilogue
    cudaStreamWaitEvent(0, eJoin, 0);
    final_kernel<<<NQ / FROWS, 256>>>(out, ga1, be1, ga2, be2);
}

// round 16
// speedup vs baseline: 1.0403x; 1.0154x over previous
#include <cuda_runtime.h>
#include <cuda_bf16.h>
#include <cstdint>

// Problem constants
#define CB      4          // batches
#define N1C     16384      // queries per batch
#define N2C     4096       // points per batch
#define NQ      (CB*N1C)   // 65536
#define NP      (CB*N2C)   // 16384
#define COUTC   256
#define GRIDG   16
#define NCELL   (GRIDG*GRIDG*GRIDG)  // 4096

__device__ __forceinline__ uint32_t smem_to_u32(const void* smem_ptr) {
    uint32_t addr;
    asm("{ .reg .u64 tmp; cvta.to.shared.u64 tmp, %1; cvt.u32.u64 %0, tmp; }"
        : "=r"(addr) : "l"(smem_ptr));
    return addr;
}
__device__ __forceinline__ void ldm_x4(uint32_t* r, uint32_t addr) {
    asm volatile("ldmatrix.sync.aligned.m8n8.x4.shared.b16 {%0,%1,%2,%3}, [%4];"
        : "=r"(r[0]), "=r"(r[1]), "=r"(r[2]), "=r"(r[3]) : "r"(addr));
}
__device__ __forceinline__ void mma_bf16(float* c, const uint32_t* a, const uint32_t* b) {
    asm volatile("mma.sync.aligned.m16n8k16.row.col.f32.bf16.bf16.f32 "
        "{%0,%1,%2,%3}, {%4,%5,%6,%7}, {%8,%9}, {%0,%1,%2,%3};"
        : "+f"(c[0]), "+f"(c[1]), "+f"(c[2]), "+f"(c[3])
        : "r"(a[0]), "r"(a[1]), "r"(a[2]), "r"(a[3]), "r"(b[0]), "r"(b[1]));
}
__device__ __forceinline__ void cp_async16(uint32_t dst, const void* src) {
    asm volatile("cp.async.cg.shared.global [%0], [%1], 16;" :: "r"(dst), "l"(src));
}
#define CP_COMMIT() asm volatile("cp.async.commit_group;" ::: "memory")
#define CP_WAIT0()  asm volatile("cp.async.wait_group 0;" ::: "memory")

__device__ __forceinline__ uint32_t pack_bf2(__nv_bfloat16 a, __nv_bfloat16 b) {
    __nv_bfloat162 t(a, b);
    return *reinterpret_cast<uint32_t*>(&t);
}

// ---------------- device scratch (static — no allocation allowed) ------------
__device__ float  g_f2pre[NP * COUTC];         // 16 MB pre-activation of branch 2
__device__ __nv_bfloat16 g_W1h[256 * 256];     // transposed [N][K]
__device__ __nv_bfloat16 g_W1l[256 * 256];
__device__ __nv_bfloat16 g_W2h[256 * 512];
__device__ __nv_bfloat16 g_W2l[256 * 512];
__device__ float  g_psum1[512 * COUTC];
__device__ float  g_psq1 [512 * COUTC];
__device__ float  g_psum2[128 * COUTC];
__device__ float  g_psq2 [128 * COUTC];
__device__ float  g_mean1[COUTC], g_rstd1[COUTC];
__device__ float  g_mean2[COUTC], g_rstd2[COUTC];
__device__ int    g_cnt[CB * NCELL];
__device__ int    g_cellStart[CB * (NCELL + 1)];
__device__ int    g_cellPtr[CB * NCELL];
__device__ float4 g_sortedPts[CB * N2C];       // x,y,z,|p|^2  (cell-sorted)
__device__ int    g_sortedIdx[CB * N2C];       // original row index (global)
__device__ int    g_qcnt[CB * NCELL];
__device__ int    g_qptr[CB * NCELL];
__device__ float4 g_sortedQ[NQ];               // x,y,z,|q|^2  (cell-sorted queries)
__device__ int    g_sortedQid[NQ];
__device__ int    g_knnIdx[NQ * 3];            // indexed by SORTED position
__device__ float  g_knnW [NQ * 3];             // indexed by SORTED position

// Both weight transposes + hi/lo splits in one launch.
__global__ __launch_bounds__(256) void wt_split_all_kernel(
    const float* __restrict__ W1, const float* __restrict__ W2)
{
    int i = blockIdx.x * 256 + threadIdx.x;
    if (i < 256 * 256) {
        int k = i >> 8, n = i & 255;
        float x = W1[i];
        __nv_bfloat16 h = __float2bfloat16_rn(x);
        g_W1h[n * 256 + k] = h;
        g_W1l[n * 256 + k] = __float2bfloat16_rn(x - __bfloat162float(h));
    } else {
        int j = i - 256 * 256;
        if (j >= 512 * 256) return;
        int k = j >> 8, n = j & 255;
        float x = W2[j];
        __nv_bfloat16 h = __float2bfloat16_rn(x);
        g_W2h[n * 512 + k] = h;
        g_W2l[n * 512 + k] = __float2bfloat16_rn(x - __bfloat162float(h));
    }
}

// ---------------- mma.sync bf16x3 GEMM: double-buffered pipeline -------------
#define PITCH 40                    // bf16 per smem row (80B — conflict-free ldmatrix)
#define TILEB 10240                 // one 128xPITCH bf16 tile in bytes
#define DB_AH 0
#define DB_AL TILEB
#define DB_BH (2*TILEB)
#define DB_BL (3*TILEB)
#define DB_BUF (4*TILEB)            // bytes per buffer (40960)
#define DB_S   (8*TILEB)            // sS after both buffers
#define DB_Q   (8*TILEB + 1024)
#define DB_TOTAL (8*TILEB + 2048)   // 83968 bytes

template<int K>
__global__ __launch_bounds__(256, 2) void gemm_mma_kernel(
    const float* __restrict__ A,
    const __nv_bfloat16* __restrict__ Bh, const __nv_bfloat16* __restrict__ Bl,
    const float* __restrict__ bias, float* __restrict__ C,
    float* __restrict__ ps, float* __restrict__ pq)
{
    extern __shared__ char dsm[];
    const uint32_t base = smem_to_u32(dsm);
    float (*sS)[32] = (float(*)[32])(dsm + DB_S);
    float (*sQ)[32] = (float(*)[32])(dsm + DB_Q);

    const int tid = threadIdx.x, lane = tid & 31, wid = tid >> 5;
    const int wm = wid & 1, wn = wid >> 1;      // warp grid: 2 (m) x 4 (n)
    const int m0 = blockIdx.y * 128, n0 = blockIdx.x * 128;

    float acc[4][4][4];
#pragma unroll
    for (int i = 0; i < 4; i++)
#pragma unroll
        for (int j = 0; j < 4; j++)
#pragma unroll
            for (int k = 0; k < 4; k++) acc[i][j][k] = 0.f;

    const uint32_t aoff = ((uint32_t)((wm * 64 + (lane & 15)) * PITCH + (lane >> 4) * 8)) * 2;
    // b lane offset valid for all 32 lanes: (lane&7) row, ((lane>>3)&1) k-half
    const uint32_t boff = ((uint32_t)((wn * 32 + (lane & 7)) * PITCH + ((lane >> 3) & 1) * 8)) * 2;
    const bool blo = lane >= 16;    // lanes 16-31 fetch the LO tile in fused ldm_x4

    float4 ra[4];   // A stage regs (held across compute in steady state)

    auto issueB = [&](int kt, int buf) {
        uint32_t dbh = base + buf * DB_BUF + DB_BH;
        uint32_t dbl = base + buf * DB_BUF + DB_BL;
        int k0 = kt * 32;
#pragma unroll
        for (int i = 0; i < 2; i++) {
            int fid = i * 256 + tid, r = fid >> 2, q = fid & 3;
            size_t gb = (size_t)(n0 + r) * K + k0 + q * 8;
            uint32_t so = (uint32_t)(r * PITCH + q * 8) * 2;
            cp_async16(dbh + so, Bh + gb);
            cp_async16(dbl + so, Bl + gb);
        }
        CP_COMMIT();
    };
    auto loadA = [&](int kt) {
        int k0 = kt * 32;
#pragma unroll
        for (int i = 0; i < 4; i++) {
            int fid = i * 256 + tid, r = fid >> 3, q = fid & 7;
            ra[i] = *(const float4*)(A + (size_t)(m0 + r) * K + k0 + q * 4);
        }
    };
    auto storeA = [&](int buf) {
        __nv_bfloat16* sAh = (__nv_bfloat16*)(dsm + buf * DB_BUF + DB_AH);
        __nv_bfloat16* sAl = (__nv_bfloat16*)(dsm + buf * DB_BUF + DB_AL);
#pragma unroll
        for (int i = 0; i < 4; i++) {
            int fid = i * 256 + tid, r = fid >> 3, q = fid & 7;
            float4 v = ra[i];
            __nv_bfloat16 h0 = __float2bfloat16_rn(v.x);
            __nv_bfloat16 h1 = __float2bfloat16_rn(v.y);
            __nv_bfloat16 h2 = __float2bfloat16_rn(v.z);
            __nv_bfloat16 h3 = __float2bfloat16_rn(v.w);
            __nv_bfloat16 l0 = __float2bfloat16_rn(v.x - __bfloat162float(h0));
            __nv_bfloat16 l1 = __float2bfloat16_rn(v.y - __bfloat162float(h1));
            __nv_bfloat16 l2 = __float2bfloat16_rn(v.z - __bfloat162float(h2));
            __nv_bfloat16 l3 = __float2bfloat16_rn(v.w - __bfloat162float(h3));
            int so = r * PITCH + q * 4;
            uint2 ph, pl;
            ph.x = pack_bf2(h0, h1); ph.y = pack_bf2(h2, h3);
            pl.x = pack_bf2(l0, l1); pl.y = pack_bf2(l2, l3);
            *(uint2*)(sAh + so) = ph;
            *(uint2*)(sAl + so) = pl;
        }
    };
    auto compute = [&](int buf) {
        uint32_t uAh = base + buf * DB_BUF + DB_AH;
        uint32_t uAl = base + buf * DB_BUF + DB_AL;
        uint32_t uBh = base + buf * DB_BUF + DB_BH;
        uint32_t uBl = base + buf * DB_BUF + DB_BL;
        uint32_t bsel = (blo ? uBl : uBh) + boff;   // fused ldm_x4: lanes 0-15 HI, 16-31 LO
#pragma unroll
        for (int ks = 0; ks < 2; ks++) {
            uint32_t bf[4][4];   // [nt][0..1]=hi frags, [2..3]=lo frags
#pragma unroll
            for (int nt = 0; nt < 4; nt++) {
                uint32_t o = (uint32_t)(nt * 8 * PITCH + ks * 16) * 2;
                ldm_x4(bf[nt], bsel + o);
            }
#pragma unroll
            for (int mt = 0; mt < 4; mt++) {
                uint32_t afh[4], afl[4];
                uint32_t o = aoff + (uint32_t)(mt * 16 * PITCH + ks * 16) * 2;
                ldm_x4(afh, uAh + o);
                ldm_x4(afl, uAl + o);
#pragma unroll
                for (int nt = 0; nt < 4; nt++) {
                    mma_bf16(acc[mt][nt], afh, &bf[nt][0]);   // hh
                    mma_bf16(acc[mt][nt], afh, &bf[nt][2]);   // hl
                    mma_bf16(acc[mt][nt], afl, &bf[nt][0]);   // lh
                }
            }
        }
    };

    const int NIT = K / 32;
    issueB(0, 0);
    loadA(0);
    storeA(0);
    CP_WAIT0();
    __syncthreads();

    for (int kt = 0; kt < NIT; kt++) {
        int cur = kt & 1, nxt = cur ^ 1;
        if (kt + 1 < NIT) {
            issueB(kt + 1, nxt);   // cp.async — overlaps compute below
            loadA(kt + 1);         // LDGs in flight across compute
        }
        compute(cur);
        if (kt + 1 < NIT) {
            storeA(nxt);           // convert + store into alternate buffer
            CP_WAIT0();
        }
        __syncthreads();
    }

    // epilogue: bias add, store C, per-block column sum/sumsq
    const int tr = lane >> 2, tc = (lane & 3) * 2;
    const int rbase = m0 + wm * 64, cbase = n0 + wn * 32;
#pragma unroll
    for (int nt = 0; nt < 4; nt++) {
        int col = cbase + nt * 8 + tc;
        float bx = bias[col], by = bias[col + 1];
        float s0 = 0.f, s1 = 0.f, q0 = 0.f, q1 = 0.f;
#pragma unroll
        for (int mt = 0; mt < 4; mt++) {
            int row = rbase + mt * 16 + tr;
            float v0 = acc[mt][nt][0] + bx, v1 = acc[mt][nt][1] + by;
            float v2 = acc[mt][nt][2] + bx, v3 = acc[mt][nt][3] + by;
            *(float2*)(C + (size_t)row * 256 + col) = make_float2(v0, v1);
            *(float2*)(C + (size_t)(row + 8) * 256 + col) = make_float2(v2, v3);
            s0 += v0 + v2; s1 += v1 + v3;
            q0 = fmaf(v0, v0, q0); q0 = fmaf(v2, v2, q0);
            q1 = fmaf(v1, v1, q1); q1 = fmaf(v3, v3, q1);
        }
#pragma unroll
        for (int off = 4; off <= 16; off <<= 1) {
            s0 += __shfl_xor_sync(0xffffffff, s0, off);
            s1 += __shfl_xor_sync(0xffffffff, s1, off);
            q0 += __shfl_xor_sync(0xffffffff, q0, off);
            q1 += __shfl_xor_sync(0xffffffff, q1, off);
        }
        if (tr == 0) {
            int lc = nt * 8 + tc;
            sS[wid][lc] = s0; sS[wid][lc + 1] = s1;
            sQ[wid][lc] = q0; sQ[wid][lc + 1] = q1;
        }
    }
    __syncthreads();
    if (tid < 128) {
        int wn2 = tid >> 5, col = tid & 31;
        float s = sS[wn2 * 2][col] + sS[wn2 * 2 + 1][col];
        float q = sQ[wn2 * 2][col] + sQ[wn2 * 2 + 1][col];
        int gc = n0 + wn2 * 32 + col;
        ps[(size_t)blockIdx.y * 256 + gc] = s;
        pq[(size_t)blockIdx.y * 256 + gc] = q;
    }
}

// ---------------- BN stats final reduce, both sets in one launch -------------
__global__ __launch_bounds__(128) void colstats_final_all_kernel()
{
    int bc = blockIdx.x, t = threadIdx.x;
    const float* ps; const float* pq; float* mean; float* rstd;
    int nch; float invR; int c;
    if (bc < 256) {
        c = bc; ps = g_psum1; pq = g_psq1; mean = g_mean1; rstd = g_rstd1;
        nch = NQ / 128; invR = 1.f / (float)NQ;
    } else {
        c = bc - 256; ps = g_psum2; pq = g_psq2; mean = g_mean2; rstd = g_rstd2;
        nch = NP / 128; invR = 1.f / (float)NP;
    }
    float s = 0.f, q = 0.f;
    for (int i = t; i < nch; i += 128) { s += ps[i * COUTC + c]; q += pq[i * COUTC + c]; }
    __shared__ float ss[128], sq[128];
    ss[t] = s; sq[t] = q;
    __syncthreads();
    for (int o = 64; o > 0; o >>= 1) {
        if (t < o) { ss[t] += ss[t + o]; sq[t] += sq[t + o]; }
        __syncthreads();
    }
    if (t == 0) {
        float mu = ss[0] * invR;
        float var = sq[0] * invR - mu * mu;
        mean[c] = mu;
        rstd[c] = rsqrtf(var + 1e-5f);
    }
}

// ---------------- grid build ------------------------------------------------
__device__ __forceinline__ int cell_of(float x, float y, float z, int* cx, int* cy, int* cz)
{
    int ix = min(max((int)(x * 16.f), 0), 15);
    int iy = min(max((int)(y * 16.f), 0), 15);
    int iz = min(max((int)(z * 16.f), 0), 15);
    *cx = ix; *cy = iy; *cz = iz;
    return (iz << 8) + (iy << 4) + ix;
}

__global__ void grid_zero_kernel()
{
    int i = blockIdx.x * 256 + threadIdx.x;
    if (i < CB * NCELL) { g_cnt[i] = 0; g_qcnt[i] = 0; }
}

__global__ void count_all_kernel(const float* __restrict__ p2, const float* __restrict__ p1)
{
    int cx, cy, cz;
    if (blockIdx.x < 64) {
        int i = blockIdx.x * 256 + threadIdx.x;
        float x = p2[i * 3], y = p2[i * 3 + 1], z = p2[i * 3 + 2];
        int cell = cell_of(x, y, z, &cx, &cy, &cz);
        atomicAdd(&g_cnt[(i >> 12) * NCELL + cell], 1);
    } else {
        int i = (blockIdx.x - 64) * 256 + threadIdx.x;
        float x = p1[i * 3], y = p1[i * 3 + 1], z = p1[i * 3 + 2];
        int cell = cell_of(x, y, z, &cx, &cy, &cz);
        atomicAdd(&g_qcnt[(i >> 14) * NCELL + cell], 1);
    }
}

__global__ __launch_bounds__(1024) void scan_all_kernel()
{
    __shared__ int ts[1024];
    bool isQ = blockIdx.x >= 4;
    int b = isQ ? blockIdx.x - 4 : blockIdx.x;
    const int* cnt = isQ ? g_qcnt : g_cnt;
    int* ptr = isQ ? g_qptr : g_cellPtr;
    int t = threadIdx.x;
    int v0 = cnt[b * NCELL + t * 4 + 0];
    int v1 = cnt[b * NCELL + t * 4 + 1];
    int v2 = cnt[b * NCELL + t * 4 + 2];
    int v3 = cnt[b * NCELL + t * 4 + 3];
    int loc = v0 + v1 + v2 + v3;
    ts[t] = loc;
    __syncthreads();
    for (int off = 1; off < 1024; off <<= 1) {
        int add = (t >= off) ? ts[t - off] : 0;
        __syncthreads();
        ts[t] += add;
        __syncthreads();
    }
    int p = ts[t] - loc;
    if (!isQ) {
        int base = b * (NCELL + 1);
        g_cellStart[base + t * 4 + 0] = p;
        g_cellStart[base + t * 4 + 1] = p + v0;
        g_cellStart[base + t * 4 + 2] = p + v0 + v1;
        g_cellStart[base + t * 4 + 3] = p + v0 + v1 + v2;
        if (t == 1023) g_cellStart[base + NCELL] = ts[1023];
    }
    ptr[b * NCELL + t * 4 + 0] = p;         p += v0;
    ptr[b * NCELL + t * 4 + 1] = p;         p += v1;
    ptr[b * NCELL + t * 4 + 2] = p;         p += v2;
    ptr[b * NCELL + t * 4 + 3] = p;
}

__global__ void scatter_all_kernel(const float* __restrict__ p2, const float* __restrict__ p1)
{
    int cx, cy, cz;
    if (blockIdx.x < 64) {
        int i = blockIdx.x * 256 + threadIdx.x;
        int b = i >> 12;
        float x = p2[i * 3], y = p2[i * 3 + 1], z = p2[i * 3 + 2];
        float pp = __fadd_rn(__fadd_rn(__fmul_rn(x, x), __fmul_rn(y, y)), __fmul_rn(z, z));
        int cell = cell_of(x, y, z, &cx, &cy, &cz);
        int pos = atomicAdd(&g_cellPtr[b * NCELL + cell], 1);
        g_sortedPts[b * N2C + pos] = make_float4(x, y, z, pp);
        g_sortedIdx[b * N2C + pos] = i;
    } else {
        int i = (blockIdx.x - 64) * 256 + threadIdx.x;
        int b = i >> 14;
        float x = p1[i * 3], y = p1[i * 3 + 1], z = p1[i * 3 + 2];
        float qq = __fadd_rn(__fadd_rn(__fmul_rn(x, x), __fmul_rn(y, y)), __fmul_rn(z, z));
        int cell = cell_of(x, y, z, &cx, &cy, &cz);
        int pos = atomicAdd(&g_qptr[b * NCELL + cell], 1);
        g_sortedQ[b * N1C + pos] = make_float4(x, y, z, qq);
        g_sortedQid[b * N1C + pos] = i;
    }
}

__global__ void grid_sortfix_kernel()
{
    int t = blockIdx.x * 256 + threadIdx.x;
    if (t >= CB * NCELL) return;
    int b = t >> 12, cell = t & 4095;
    int s = g_cellStart[b * (NCELL + 1) + cell];
    int e = g_cellStart[b * (NCELL + 1) + cell + 1];
    int base = b * N2C;
    for (int a = s + 1; a < e; a++) {
        int ia = g_sortedIdx[base + a];
        float4 pa = g_sortedPts[base + a];
        int k = a - 1;
        while (k >= s && g_sortedIdx[base + k] > ia) {
            g_sortedIdx[base + k + 1] = g_sortedIdx[base + k];
            g_sortedPts[base + k + 1] = g_sortedPts[base + k];
            k--;
        }
        g_sortedIdx[base + k + 1] = ia;
        g_sortedPts[base + k + 1] = pa;
    }
}

// ---------------- KNN (K=3): ring expansion with EXACT box-face bound --------
// Results stored by SORTED position (coalesced); final maps pos -> qid.
__global__ __launch_bounds__(256) void knn_kernel()
{
    extern __shared__ unsigned char smraw[];
    float4* sp = (float4*)smraw;                                  // 4096 float4
    int* cs  = (int*)(smraw + N2C * sizeof(float4));              // 4097 ints
    int* sid = (int*)(smraw + N2C * sizeof(float4) + (NCELL + 16) * sizeof(int)); // 4096 ints

    int pos = blockIdx.x * 256 + threadIdx.x;
    int batch = pos >> 14;
    for (int i = threadIdx.x; i < N2C; i += 256) {
        sp[i]  = g_sortedPts[batch * N2C + i];
        sid[i] = g_sortedIdx[batch * N2C + i];
    }
    for (int i = threadIdx.x; i < NCELL + 1; i += 256)
        cs[i] = g_cellStart[batch * (NCELL + 1) + i];
    __syncthreads();

    float4 qv = g_sortedQ[pos];
    float qx = qv.x, qy = qv.y, qz = qv.z, qq = qv.w;

    int cx, cy, cz;
    (void)cell_of(qx, qy, qz, &cx, &cy, &cz);

    float b0 = 3.4e38f, b1 = 3.4e38f, b2 = 3.4e38f;
    int i0 = 0x7fffffff, i1 = 0x7fffffff, i2 = 0x7fffffff;

    auto proc = [&](int s, int e) {
        for (int j = s; j < e; j++) {
            float4 p = sp[j];
            int oi = sid[j];
            float dot = fmaf(qz, p.z, fmaf(qy, p.y, __fmul_rn(qx, p.x)));
            float d2 = __fsub_rn(__fadd_rn(qq, p.w), __fmul_rn(2.0f, dot));
            bool lt2 = (d2 < b2) || (d2 == b2 && oi < i2);
            if (lt2) {
                bool lt1 = (d2 < b1) || (d2 == b1 && oi < i1);
                if (lt1) {
                    b2 = b1; i2 = i1;
                    bool lt0 = (d2 < b0) || (d2 == b0 && oi < i0);
                    if (lt0) { b1 = b0; i1 = i0; b0 = d2; i0 = oi; }
                    else     { b1 = d2; i1 = oi; }
                } else { b2 = d2; i2 = oi; }
            }
        }
    };

    const float h = 0.0625f;
    for (int r = 0; ; r++) {
        int zlo = max(cz - r, 0), zhi = min(cz + r, 15);
        for (int z = zlo; z <= zhi; z++) {
            bool ze = (z == cz - r) || (z == cz + r);
            int ylo = max(cy - r, 0), yhi = min(cy + r, 15);
            for (int y = ylo; y <= yhi; y++) {
                bool ye = (y == cy - r) || (y == cy + r);
                int rb = (z << 8) + (y << 4);
                if (ze || ye) {
                    int xlo = max(cx - r, 0), xhi = min(cx + r, 15);
                    proc(cs[rb + xlo], cs[rb + xhi + 1]);   // contiguous x-span
                } else {
                    if (cx - r >= 0) proc(cs[rb + cx - r], cs[rb + cx - r + 1]);
                    if (cx + r <= 15) proc(cs[rb + cx + r], cs[rb + cx + r + 1]);
                }
            }
        }
        float bnd = 3.4e38f;
        if (cx - r - 1 >= 0) bnd = fminf(bnd, qx - (float)(cx - r) * h);
        if (cx + r + 1 <= 15) bnd = fminf(bnd, (float)(cx + r + 1) * h - qx);
        if (cy - r - 1 >= 0) bnd = fminf(bnd, qy - (float)(cy - r) * h);
        if (cy + r + 1 <= 15) bnd = fminf(bnd, (float)(cy + r + 1) * h - qy);
        if (cz - r - 1 >= 0) bnd = fminf(bnd, qz - (float)(cz - r) * h);
        if (cz + r + 1 <= 15) bnd = fminf(bnd, (float)(cz + r + 1) * h - qz);
        if (bnd > 3e38f) break;                       // whole grid covered
        if (b2 <= bnd * bnd - 1e-5f) break;           // provably done (with fp slack)
    }

    float d0 = fmaxf(b0, 0.f), d1 = fmaxf(b1, 0.f), d2c = fmaxf(b2, 0.f);
    float r0 = __fdiv_rn(1.0f, __fadd_rn(d0, 1e-8f));
    float r1 = __fdiv_rn(1.0f, __fadd_rn(d1, 1e-8f));
    float r2 = __fdiv_rn(1.0f, __fadd_rn(d2c, 1e-8f));
    float sum = __fadd_rn(__fadd_rn(r0, r1), r2);

    g_knnIdx[pos * 3 + 0] = i0;
    g_knnIdx[pos * 3 + 1] = i1;
    g_knnIdx[pos * 3 + 2] = i2;
    g_knnW[pos * 3 + 0] = __fdiv_rn(r0, sum);
    g_knnW[pos * 3 + 1] = __fdiv_rn(r1, sum);
    g_knnW[pos * 3 + 2] = __fdiv_rn(r2, sum);
}

// ---------------- final: BN+relu both branches, gather, weighted add ---------
// Processes 8 SORTED positions per block (gather locality); writes to qid rows.
#define FROWS 8
__global__ __launch_bounds__(256) void final_kernel(
    float* io,
    const float* __restrict__ ga1, const float* __restrict__ be1,
    const float* __restrict__ ga2, const float* __restrict__ be2)
{
    int pos0 = blockIdx.x * FROWS;
    int c4 = (threadIdx.x & 63) * 4;
    int rsub = threadIdx.x >> 6;           // 0..3
    __shared__ int si[FROWS][3];
    __shared__ float sw[FROWS][3];
    __shared__ int sqid[FROWS];
    if (threadIdx.x < FROWS * 3) {
        si[threadIdx.x / 3][threadIdx.x % 3] = g_knnIdx[pos0 * 3 + threadIdx.x];
        sw[threadIdx.x / 3][threadIdx.x % 3] = g_knnW[pos0 * 3 + threadIdx.x];
    }
    if (threadIdx.x < FROWS) sqid[threadIdx.x] = g_sortedQid[pos0 + threadIdx.x];
    float4 GA1 = *(const float4*)(ga1 + c4), BE1 = *(const float4*)(be1 + c4);
    float4 GA2 = *(const float4*)(ga2 + c4), BE2 = *(const float4*)(be2 + c4);
    float4 RS1 = *(const float4*)(g_rstd1 + c4), ME1 = *(const float4*)(g_mean1 + c4);
    float4 RS2 = *(const float4*)(g_rstd2 + c4), ME2 = *(const float4*)(g_mean2 + c4);
    float G1x = GA1.x * RS1.x, G1y = GA1.y * RS1.y, G1z = GA1.z * RS1.z, G1w = GA1.w * RS1.w;
    float G2x = GA2.x * RS2.x, G2y = GA2.y * RS2.y, G2z = GA2.z * RS2.z, G2w = GA2.w * RS2.w;
    __syncthreads();

#pragma unroll
    for (int rr = rsub; rr < FROWS; rr += 4) {
        int row = sqid[rr];
        float4 x = *(float4*)(io + (size_t)row * COUTC + c4);
        float vx = fmaxf(G1x * (x.x - ME1.x) + BE1.x, 0.f);
        float vy = fmaxf(G1y * (x.y - ME1.y) + BE1.y, 0.f);
        float vz = fmaxf(G1z * (x.z - ME1.z) + BE1.z, 0.f);
        float vw = fmaxf(G1w * (x.w - ME1.w) + BE1.w, 0.f);
        float ax = 0.f, ay = 0.f, az = 0.f, aw = 0.f;
#pragma unroll
        for (int k = 0; k < 3; k++) {
            float4 y = *(const float4*)(g_f2pre + (size_t)si[rr][k] * COUTC + c4);
            float w = sw[rr][k];
            ax = fmaf(w, fmaxf(G2x * (y.x - ME2.x) + BE2.x, 0.f), ax);
            ay = fmaf(w, fmaxf(G2y * (y.y - ME2.y) + BE2.y, 0.f), ay);
            az = fmaf(w, fmaxf(G2z * (y.z - ME2.z) + BE2.z, 0.f), az);
            aw = fmaf(w, fmaxf(G2w * (y.w - ME2.w) + BE2.w, 0.f), aw);
        }
        float4 o;
        o.x = vx + ax; o.y = vy + ay; o.z = vz + az; o.w = vw + aw;
        *(float4*)(io + (size_t)row * COUTC + c4) = o;
    }
}

// ---------------- launch ----------------------------------------------------
extern "C" void kernel_launch(void* const* d_in, const int* in_sizes, int n_in,
                              void* d_out, int out_size)
{
    const float* p1  = (const float*)d_in[0];
    const float* f1  = (const float*)d_in[1];
    const float* p2  = (const float*)d_in[2];
    const float* f2  = (const float*)d_in[3];
    const float* W1  = (const float*)d_in[4];
    const float* b1  = (const float*)d_in[5];
    const float* ga1 = (const float*)d_in[6];
    const float* be1 = (const float*)d_in[7];
    const float* W2  = (const float*)d_in[8];
    const float* b2  = (const float*)d_in[9];
    const float* ga2 = (const float*)d_in[10];
    const float* be2 = (const float*)d_in[11];
    float* out = (float*)d_out;

    float *f2pre, *ps1, *pq1, *ps2, *pq2;
    __nv_bfloat16 *w1h, *w1l, *w2h, *w2l;
    cudaGetSymbolAddress((void**)&f2pre, g_f2pre);
    cudaGetSymbolAddress((void**)&ps1, g_psum1);
    cudaGetSymbolAddress((void**)&pq1, g_psq1);
    cudaGetSymbolAddress((void**)&ps2, g_psum2);
    cudaGetSymbolAddress((void**)&pq2, g_psq2);
    cudaGetSymbolAddress((void**)&w1h, g_W1h);
    cudaGetSymbolAddress((void**)&w1l, g_W1l);
    cudaGetSymbolAddress((void**)&w2h, g_W2h);
    cudaGetSymbolAddress((void**)&w2l, g_W2l);

    // fork/join: chain B (grid+KNN) on a high-priority side stream
    int prLo, prHi;
    cudaDeviceGetStreamPriorityRange(&prLo, &prHi);
    cudaStream_t s2;
    cudaEvent_t eFork, eJoin;
    cudaStreamCreateWithPriority(&s2, cudaStreamNonBlocking, prHi);
    cudaEventCreateWithFlags(&eFork, cudaEventDisableTiming);
    cudaEventCreateWithFlags(&eJoin, cudaEventDisableTiming);

    size_t sm = N2C * sizeof(float4) + (NCELL + 16) * sizeof(int) + N2C * sizeof(int);
    cudaFuncSetAttribute(knn_kernel, cudaFuncAttributeMaxDynamicSharedMemorySize, (int)sm);
    cudaFuncSetAttribute(gemm_mma_kernel<256>, cudaFuncAttributeMaxDynamicSharedMemorySize, DB_TOTAL);
    cudaFuncSetAttribute(gemm_mma_kernel<512>, cudaFuncAttributeMaxDynamicSharedMemorySize, DB_TOTAL);

    // fork
    cudaEventRecord(eFork, 0);
    cudaStreamWaitEvent(s2, eFork, 0);

    // chain B (side stream): spatial grids + KNN
    grid_zero_kernel<<<64, 256, 0, s2>>>();
    count_all_kernel<<<320, 256, 0, s2>>>(p2, p1);
    scan_all_kernel<<<8, 1024, 0, s2>>>();
    scatter_all_kernel<<<320, 256, 0, s2>>>(p2, p1);
    grid_sortfix_kernel<<<64, 256, 0, s2>>>();
    knn_kernel<<<256, 256, sm, s2>>>();
    cudaEventRecord(eJoin, s2);

    // chain A (main stream): weight split + GEMMs + BN stats
    wt_split_all_kernel<<<768, 256>>>(W1, W2);
    gemm_mma_kernel<512><<<dim3(2, NP / 128), 256, DB_TOTAL>>>(f2, w2h, w2l, b2, f2pre, ps2, pq2);
    gemm_mma_kernel<256><<<dim3(2, NQ / 128), 256, DB_TOTAL>>>(f1, w1h, w1l, b1, out, ps1, pq1);
    colstats_final_all_kernel<<<512, 128>>>();

    // join + fused epilogue
    cudaStreamWaitEvent(0, eJoin, 0);
    final_kernel<<<NQ / FROWS, 256>>>(out, ga1, be1, ga2, be2);
}